// round 16
// baseline (speedup 1.0000x reference)
#include <cuda_runtime.h>
#include <cuda_bf16.h>
#include <cuda_fp16.h>
#include <cstdint>

#define N_NODES 50000
#define N_EDGES 800000

#define NT128 ((N_NODES + 127) / 128)                // 391

#define CSR_BLOCKS 148
#define CSR_THREADS 256
#define CSR_NTH (CSR_BLOCKS * CSR_THREADS)           // 37888
#define SEG ((N_NODES + CSR_BLOCKS - 1) / CSR_BLOCKS) // 338
#define SEG_C ((SEG + CSR_THREADS - 1) / CSR_THREADS) // 2

typedef unsigned long long ull;

// ---------------- device scratch (static, no allocation) ----------------
__device__ uint32_t g_v16[N_NODES * 64];   // layer1 v, half2 pairs (256 B/row)
__device__ float    g_s  [N_NODES * 128];  // layer1 s (= x.Wroot1 + b1), fp32
__device__ uint32_t g_t16[N_NODES * 64];   // layer1 activations, half2 (256 B/row)
__device__ uint32_t g_u16[N_NODES * 32];   // layer2 u, half2 pairs (128 B/row)
__device__ float    g_r  [N_NODES * 64];   // layer2 r (= t1.Wroot2 + b2), fp32
__device__ int      g_deg[N_NODES];
__device__ int      g_off[N_NODES + 1];
__device__ int      g_cursor[N_NODES];
__device__ int      g_csr[N_EDGES];
__device__ int      g_bsum[CSR_BLOCKS];
__device__ int      g_is64;
__device__ unsigned int g_barc;
__device__ volatile unsigned int g_gen;

// ================= software grid barrier (all CSR_BLOCKS co-resident) =================
__device__ __forceinline__ void gsync() {
    __syncthreads();
    if (threadIdx.x == 0) {
        __threadfence();
        unsigned int gen = g_gen;
        if (atomicAdd(&g_barc, 1u) == (unsigned)CSR_BLOCKS - 1u) {
            g_barc = 0u;
            __threadfence();
            g_gen = gen + 1u;
        } else {
            while (g_gen == gen) { __nanosleep(64); }
            __threadfence();
        }
    }
    __syncthreads();
}

// ================= fused CSR build: one persistent kernel =================
__global__ void __launch_bounds__(CSR_THREADS, 1)
k_csr(const void* __restrict__ ei) {
    __shared__ int sh[CSR_THREADS];
    const int t = threadIdx.x;
    const int bid = blockIdx.x;
    const int tid_g = bid * CSR_THREADS + t;

    // ---- phase 0: zero degrees + dtype detect ----
    for (int i = tid_g; i < N_NODES; i += CSR_NTH) g_deg[i] = 0;
    if (tid_g == 0) {
        const int* e32 = (const int*)ei;
        int orv = 0;
#pragma unroll
        for (int k = 0; k < 64; k++) orv |= e32[2 * k + 1];
        g_is64 = (orv == 0) ? 1 : 0;
    }
    gsync();

    const int is64 = g_is64;

    // ---- phase 1: histogram (4 edges per step, MLP=4) ----
    for (int e0 = tid_g * 4; e0 < N_EDGES; e0 += CSR_NTH * 4) {
        int d0, d1, d2, d3;
        if (is64) {
            const longlong2* p = (const longlong2*)((const long long*)ei + N_EDGES);
            longlong2 a = p[e0 >> 1];
            longlong2 b = p[(e0 >> 1) + 1];
            d0 = (int)a.x; d1 = (int)a.y; d2 = (int)b.x; d3 = (int)b.y;
        } else {
            int4 a = *(const int4*)((const int*)ei + N_EDGES + e0);
            d0 = a.x; d1 = a.y; d2 = a.z; d3 = a.w;
        }
        atomicAdd(&g_deg[d0], 1);
        atomicAdd(&g_deg[d1], 1);
        atomicAdd(&g_deg[d2], 1);
        atomicAdd(&g_deg[d3], 1);
    }
    gsync();

    // ---- phase 2: per-block segment scan (segment = SEG contiguous nodes) ----
    const int seg0 = bid * SEG;
    int idx0 = seg0 + t * SEG_C;
    int d[SEG_C];
    int ssum = 0;
#pragma unroll
    for (int c = 0; c < SEG_C; c++) {
        int i = idx0 + c;
        d[c] = (i < seg0 + SEG && i < N_NODES) ? g_deg[i] : 0;
        ssum += d[c];
    }
    sh[t] = ssum;
    __syncthreads();
    for (int off = 1; off < CSR_THREADS; off <<= 1) {
        int add = (t >= off) ? sh[t - off] : 0;
        __syncthreads();
        sh[t] += add;
        __syncthreads();
    }
    int local_excl = sh[t] - ssum;
    {
        int run = local_excl;
#pragma unroll
        for (int c = 0; c < SEG_C; c++) {
            int i = idx0 + c;
            if (i < seg0 + SEG && i < N_NODES) g_off[i] = run;   // segment-local
            run += d[c];
        }
    }
    if (t == CSR_THREADS - 1) g_bsum[bid] = sh[CSR_THREADS - 1];
    gsync();

    // ---- phase 3: block 0 scans the 148 block totals (exclusive) ----
    if (bid == 0) {
        int v = (t < CSR_BLOCKS) ? g_bsum[t] : 0;
        sh[t] = v;
        __syncthreads();
        for (int off = 1; off < CSR_THREADS; off <<= 1) {
            int add = (t >= off) ? sh[t - off] : 0;
            __syncthreads();
            sh[t] += add;
            __syncthreads();
        }
        if (t < CSR_BLOCKS) g_bsum[t] = sh[t] - v;
    }
    gsync();

    // ---- phase 4: add global base, fill cursor ----
    {
        const int base = g_bsum[bid];
#pragma unroll
        for (int c = 0; c < SEG_C; c++) {
            int i = idx0 + c;
            if (i < seg0 + SEG && i < N_NODES) {
                int o = g_off[i] + base;
                g_off[i] = o;
                g_cursor[i] = o;
            }
        }
        if (tid_g == 0) g_off[N_NODES] = N_EDGES;
    }
    gsync();

    // ---- phase 5: scatter (4 edges per step) ----
    for (int e0 = tid_g * 4; e0 < N_EDGES; e0 += CSR_NTH * 4) {
        int s0, s1, s2, s3, d0, d1, d2, d3;
        if (is64) {
            const longlong2* ps = (const longlong2*)ei;
            const longlong2* pd = (const longlong2*)((const long long*)ei + N_EDGES);
            longlong2 sa = ps[e0 >> 1], sb = ps[(e0 >> 1) + 1];
            longlong2 da = pd[e0 >> 1], db = pd[(e0 >> 1) + 1];
            s0 = (int)sa.x; s1 = (int)sa.y; s2 = (int)sb.x; s3 = (int)sb.y;
            d0 = (int)da.x; d1 = (int)da.y; d2 = (int)db.x; d3 = (int)db.y;
        } else {
            int4 sa = *(const int4*)((const int*)ei + e0);
            int4 da = *(const int4*)((const int*)ei + N_EDGES + e0);
            s0 = sa.x; s1 = sa.y; s2 = sa.z; s3 = sa.w;
            d0 = da.x; d1 = da.y; d2 = da.z; d3 = da.w;
        }
        int p0 = atomicAdd(&g_cursor[d0], 1);
        int p1 = atomicAdd(&g_cursor[d1], 1);
        int p2 = atomicAdd(&g_cursor[d2], 1);
        int p3 = atomicAdd(&g_cursor[d3], 1);
        g_csr[p0] = s0;
        g_csr[p1] = s1;
        g_csr[p2] = s2;
        g_csr[p3] = s3;
    }
}

// ================= split helpers =================
__device__ __forceinline__ void decomp2(float x, float y, uint32_t& hp, uint32_t& lp) {
    __nv_bfloat16 hx = __float2bfloat16(x);
    __nv_bfloat16 hy = __float2bfloat16(y);
    float rx = x - __bfloat162float(hx);
    float ry = y - __bfloat162float(hy);
    __nv_bfloat16 lx = __float2bfloat16(rx);
    __nv_bfloat16 ly = __float2bfloat16(ry);
    hp = (uint32_t)__bfloat16_as_ushort(hx) | ((uint32_t)__bfloat16_as_ushort(hy) << 16);
    lp = (uint32_t)__bfloat16_as_ushort(lx) | ((uint32_t)__bfloat16_as_ushort(ly) << 16);
}

__device__ __forceinline__ void mma16816(float* c, const uint32_t* a, uint2 b) {
    asm volatile(
        "mma.sync.aligned.m16n8k16.row.col.f32.bf16.bf16.f32 "
        "{%0,%1,%2,%3}, {%4,%5,%6,%7}, {%8,%9}, {%0,%1,%2,%3};"
        : "+f"(c[0]), "+f"(c[1]), "+f"(c[2]), "+f"(c[3])
        : "r"(a[0]), "r"(a[1]), "r"(a[2]), "r"(a[3]), "r"(b.x), "r"(b.y));
}

__device__ __forceinline__ void mma16816h(float* c, const uint32_t* a, uint2 b) {
    asm volatile(
        "mma.sync.aligned.m16n8k16.row.col.f32.f16.f16.f32 "
        "{%0,%1,%2,%3}, {%4,%5,%6,%7}, {%8,%9}, {%0,%1,%2,%3};"
        : "+f"(c[0]), "+f"(c[1]), "+f"(c[2]), "+f"(c[3])
        : "r"(a[0]), "r"(a[1]), "r"(a[2]), "r"(a[3]), "r"(b.x), "r"(b.y));
}

__device__ __forceinline__ uint32_t pack_h2(float a, float b) {
    __half2 h = __floats2half2_rn(a, b);
    return *(uint32_t*)&h;
}

// ================= layer-1 GEMM (fp32 input, 3-pass bf16 split — R13-proven) =================
template <int NCOLS>
__global__ void __launch_bounds__(256, 1)
k_mma(const float* __restrict__ X,
      const float* __restrict__ Wa, const float* __restrict__ Wb,
      const float* __restrict__ bias,
      float* __restrict__ out32, uint32_t* __restrict__ out16) {
    constexpr int NT   = NCOLS / 8;
    constexpr int HB   = NCOLS / 2;
    constexpr int MT_W = (NCOLS == 256) ? 2 : 1;
    constexpr int NT_W = 16;
    extern __shared__ uint32_t sm[];
    uint32_t* Ah = sm;
    uint32_t* Al = sm + 8192;
    uint32_t* Bh = sm + 16384;
    uint32_t* Bl = Bh + NT * 512;

    const int tid = threadIdx.x;
    const int w = tid >> 5, lane = tid & 31;
    const int wm = (NCOLS == 256) ? (w >> 1) : w;
    const int wn = (NCOLS == 256) ? (w & 1) : 0;

    for (int idx = tid; idx < NCOLS * 64; idx += 256) {
        int h  = idx >> 6;
        int c2 = (idx & 63) << 1;
        const float* src = (h < HB) ? (Wa + h * 128 + c2) : (Wb + (h - HB) * 128 + c2);
        float2 wv = *(const float2*)src;
        uint32_t hp, lp;
        decomp2(wv.x, wv.y, hp, lp);
        int nt = h >> 3;
        int ln = ((h & 7) << 2) | ((c2 >> 1) & 3);
        int ks = c2 >> 4;
        int rg = (c2 >> 3) & 1;
        int addr = ((ks * NT + nt) * 32 + ln) * 2 + rg;
        Bh[addr] = hp;
        Bl[addr] = lp;
    }
    __syncthreads();

    for (int tile = blockIdx.x; tile < NT128; tile += gridDim.x) {
        const int n0 = tile << 7;

        for (int idx = tid; idx < 128 * 64; idx += 256) {
            int r  = idx >> 6;
            int c2 = (idx & 63) << 1;
            int n = n0 + r;
            float2 v = (n < N_NODES) ? *(const float2*)(X + (size_t)n * 128 + c2)
                                     : make_float2(0.f, 0.f);
            uint32_t hp, lp;
            decomp2(v.x, v.y, hp, lp);
            int mt = r >> 4, rr = r & 15;
            int ln = ((rr & 7) << 2) | ((c2 >> 1) & 3);
            int ks = c2 >> 4;
            int rg = ((rr >> 3) & 1) | (((c2 >> 3) & 1) << 1);
            int addr = (((ks << 3) | mt) * 32 + ln) * 4 + rg;
            Ah[addr] = hp;
            Al[addr] = lp;
        }
        __syncthreads();

        float acc[MT_W][NT_W][4];
#pragma unroll
        for (int m = 0; m < MT_W; m++)
#pragma unroll
            for (int t = 0; t < NT_W; t++)
#pragma unroll
                for (int c = 0; c < 4; c++) acc[m][t][c] = 0.f;

        const uint32_t* Ap[3] = { Ah, Ah, Al };
        const uint32_t* Bp[3] = { Bh, Bl, Bh };
#pragma unroll
        for (int p = 0; p < 3; p++) {
            const uint32_t* A = Ap[p];
            const uint32_t* B = Bp[p];
#pragma unroll
            for (int ks = 0; ks < 8; ks++) {
                uint32_t af[MT_W][4];
#pragma unroll
                for (int m = 0; m < MT_W; m++) {
                    int mt = wm * MT_W + m;
                    uint4 v = *(const uint4*)&A[(((ks << 3) | mt) * 32 + lane) * 4];
                    af[m][0] = v.x; af[m][1] = v.y; af[m][2] = v.z; af[m][3] = v.w;
                }
#pragma unroll
                for (int t = 0; t < NT_W; t++) {
                    int nt = wn * NT_W + t;
                    uint2 bv = *(const uint2*)&B[((ks * NT + nt) * 32 + lane) * 2];
#pragma unroll
                    for (int m = 0; m < MT_W; m++)
                        mma16816(acc[m][t], af[m], bv);
                }
            }
        }
        __syncthreads();

#pragma unroll
        for (int m = 0; m < MT_W; m++) {
            int row0 = n0 + (wm * MT_W + m) * 16 + (lane >> 2);
#pragma unroll
            for (int t = 0; t < NT_W; t++) {
                int col = (wn * NT_W + t) * 8 + ((lane & 3) << 1);
                if (col < HB) {
                    if (row0 < N_NODES)
                        out16[(size_t)row0 * (HB / 2) + (col >> 1)] =
                            pack_h2(acc[m][t][0], acc[m][t][1]);
                    if (row0 + 8 < N_NODES)
                        out16[(size_t)(row0 + 8) * (HB / 2) + (col >> 1)] =
                            pack_h2(acc[m][t][2], acc[m][t][3]);
                } else {
                    int cc = col - HB;
                    float bx = __ldg(&bias[cc]);
                    float by = __ldg(&bias[cc + 1]);
                    if (row0 < N_NODES)
                        *(float2*)&out32[(size_t)row0 * HB + cc] =
                            make_float2(acc[m][t][0] + bx, acc[m][t][1] + by);
                    if (row0 + 8 < N_NODES)
                        *(float2*)&out32[(size_t)(row0 + 8) * HB + cc] =
                            make_float2(acc[m][t][2] + bx, acc[m][t][3] + by);
                }
            }
        }
    }
}

// ================= layer-2 GEMM: single-pass fp16 (A = t16 exact, W single fp16) =================
__global__ void __launch_bounds__(256, 1)
k_mma2(const uint32_t* __restrict__ T16,
       const float* __restrict__ Wa, const float* __restrict__ Wb,
       const float* __restrict__ bias,
       float* __restrict__ out32, uint32_t* __restrict__ out16) {
    constexpr int NT = 16, HB = 64, NT_W = 16;
    extern __shared__ uint32_t sm[];
    uint32_t* Ah = sm;            // 8192 u32
    uint32_t* Bh = sm + 8192;     // 8192 u32

    const int tid = threadIdx.x;
    const int w = tid >> 5, lane = tid & 31;

    for (int idx = tid; idx < 128 * 64; idx += 256) {
        int h  = idx >> 6;
        int c2 = (idx & 63) << 1;
        const float* src = (h < HB) ? (Wa + h * 128 + c2) : (Wb + (h - HB) * 128 + c2);
        float2 wv = *(const float2*)src;
        uint32_t hp = pack_h2(wv.x, wv.y);
        int nt = h >> 3;
        int ln = ((h & 7) << 2) | ((c2 >> 1) & 3);
        int ks = c2 >> 4;
        int rg = (c2 >> 3) & 1;
        Bh[((ks * NT + nt) * 32 + ln) * 2 + rg] = hp;
    }
    __syncthreads();

    for (int tile = blockIdx.x; tile < NT128; tile += gridDim.x) {
        const int n0 = tile << 7;

        for (int idx = tid; idx < 128 * 64; idx += 256) {
            int r  = idx >> 6;
            int cu = idx & 63;
            int n = n0 + r;
            uint32_t a = (n < N_NODES) ? T16[(size_t)n * 64 + cu] : 0u;
            int mt = r >> 4, rr = r & 15;
            int ln = ((rr & 7) << 2) | (cu & 3);
            int ks = cu >> 3;
            int rg = ((rr >> 3) & 1) | (((cu >> 2) & 1) << 1);
            Ah[(((ks << 3) | mt) * 32 + ln) * 4 + rg] = a;
        }
        __syncthreads();

        float acc[NT_W][4];
#pragma unroll
        for (int t = 0; t < NT_W; t++)
#pragma unroll
            for (int c = 0; c < 4; c++) acc[t][c] = 0.f;

#pragma unroll
        for (int ks = 0; ks < 8; ks++) {
            uint32_t af[4];
            uint4 v = *(const uint4*)&Ah[(((ks << 3) | w) * 32 + lane) * 4];
            af[0] = v.x; af[1] = v.y; af[2] = v.z; af[3] = v.w;
#pragma unroll
            for (int t = 0; t < NT_W; t++) {
                uint2 bv = *(const uint2*)&Bh[((ks * NT + t) * 32 + lane) * 2];
                mma16816h(acc[t], af, bv);
            }
        }
        __syncthreads();

        int row0 = n0 + w * 16 + (lane >> 2);
#pragma unroll
        for (int t = 0; t < NT_W; t++) {
            int col = t * 8 + ((lane & 3) << 1);
            if (col < HB) {
                if (row0 < N_NODES)
                    out16[(size_t)row0 * (HB / 2) + (col >> 1)] =
                        pack_h2(acc[t][0], acc[t][1]);
                if (row0 + 8 < N_NODES)
                    out16[(size_t)(row0 + 8) * (HB / 2) + (col >> 1)] =
                        pack_h2(acc[t][2], acc[t][3]);
            } else {
                int cc = col - HB;
                float bx = __ldg(&bias[cc]);
                float by = __ldg(&bias[cc + 1]);
                if (row0 < N_NODES)
                    *(float2*)&out32[(size_t)row0 * HB + cc] =
                        make_float2(acc[t][0] + bx, acc[t][1] + by);
                if (row0 + 8 < N_NODES)
                    *(float2*)&out32[(size_t)(row0 + 8) * HB + cc] =
                        make_float2(acc[t][2] + bx, acc[t][3] + by);
            }
        }
    }
}

// ================= aggregations =================
// t16[n] = relu( s[n] + sum_{src} v16[src] ) packed to half2; unroll 8
__global__ void k_agg1(const uint2* __restrict__ v16, const float4* __restrict__ s,
                       uint2* __restrict__ t16) {
    int gw = (blockIdx.x * blockDim.x + threadIdx.x) >> 5;
    int lane = threadIdx.x & 31;
    if (gw >= N_NODES) return;
    int beg = g_off[gw], end = g_off[gw + 1];
    float4 acc = s[gw * 32 + lane];
    int j = beg;
    for (; j + 8 <= end; j += 8) {
        uint2 rv[8];
#pragma unroll
        for (int q = 0; q < 8; q++) rv[q] = v16[g_csr[j + q] * 32 + lane];
#pragma unroll
        for (int q = 0; q < 8; q++) {
            float2 lo = __half22float2(*(const __half2*)&rv[q].x);
            float2 hi = __half22float2(*(const __half2*)&rv[q].y);
            acc.x += lo.x; acc.y += lo.y; acc.z += hi.x; acc.w += hi.y;
        }
    }
    for (; j < end; j++) {
        uint2 a = v16[g_csr[j] * 32 + lane];
        float2 lo = __half22float2(*(const __half2*)&a.x);
        float2 hi = __half22float2(*(const __half2*)&a.y);
        acc.x += lo.x; acc.y += lo.y; acc.z += hi.x; acc.w += hi.y;
    }
    acc.x = fmaxf(acc.x, 0.f); acc.y = fmaxf(acc.y, 0.f);
    acc.z = fmaxf(acc.z, 0.f); acc.w = fmaxf(acc.w, 0.f);
    uint2 o;
    o.x = pack_h2(acc.x, acc.y);
    o.y = pack_h2(acc.z, acc.w);
    t16[gw * 32 + lane] = o;
}

// out[n] = r[n] + sum_{src} u16[src]; unroll 8
__global__ void k_agg2(const uint32_t* __restrict__ u16, const float2* __restrict__ r,
                       float2* __restrict__ out) {
    int gw = (blockIdx.x * blockDim.x + threadIdx.x) >> 5;
    int lane = threadIdx.x & 31;
    if (gw >= N_NODES) return;
    int beg = g_off[gw], end = g_off[gw + 1];
    float2 acc = r[gw * 32 + lane];
    int j = beg;
    for (; j + 8 <= end; j += 8) {
        uint32_t rv[8];
#pragma unroll
        for (int q = 0; q < 8; q++) rv[q] = u16[g_csr[j + q] * 32 + lane];
#pragma unroll
        for (int q = 0; q < 8; q++) {
            float2 av = __half22float2(*(const __half2*)&rv[q]);
            acc.x += av.x; acc.y += av.y;
        }
    }
    for (; j < end; j++) {
        uint32_t a = u16[g_csr[j] * 32 + lane];
        float2 av = __half22float2(*(const __half2*)&a);
        acc.x += av.x; acc.y += av.y;
    }
    out[gw * 32 + lane] = acc;
}

// ================= launch =================
extern "C" void kernel_launch(void* const* d_in, const int* in_sizes, int n_in,
                              void* d_out, int out_size) {
    const float* x      = (const float*)d_in[0];
    const void*  ei     = d_in[1];
    const float* Wrel1  = (const float*)d_in[2];
    const float* Wroot1 = (const float*)d_in[3];
    const float* b1     = (const float*)d_in[4];
    const float* Wrel2  = (const float*)d_in[5];
    const float* Wroot2 = (const float*)d_in[6];
    const float* b2     = (const float*)d_in[7];

    void *p_v16 = nullptr, *p_s = nullptr, *p_t16 = nullptr;
    void *p_u16 = nullptr, *p_r = nullptr;
    cudaGetSymbolAddress(&p_v16, g_v16);
    cudaGetSymbolAddress(&p_s, g_s);
    cudaGetSymbolAddress(&p_t16, g_t16);
    cudaGetSymbolAddress(&p_u16, g_u16);
    cudaGetSymbolAddress(&p_r, g_r);

    const int SM1 = (16384 + 2 * 32 * 512) * 4;   // 196,608 B (A hi/lo + B hi/lo)
    const int SM2 = 16384 * 4;                    //  65,536 B
    cudaFuncSetAttribute((const void*)k_mma<256>,
                         cudaFuncAttributeMaxDynamicSharedMemorySize, SM1);
    cudaFuncSetAttribute((const void*)k_mma2,
                         cudaFuncAttributeMaxDynamicSharedMemorySize, SM2);

    static cudaStream_t s1 = nullptr;
    static cudaEvent_t evRoot = nullptr, evCsr = nullptr;
    if (s1 == nullptr) {
        cudaStreamCreateWithFlags(&s1, cudaStreamNonBlocking);
        cudaEventCreateWithFlags(&evRoot, cudaEventDisableTiming);
        cudaEventCreateWithFlags(&evCsr, cudaEventDisableTiming);
    }

    // fork: fused CSR build on s1, concurrent with layer-1 GEMM on stream 0
    cudaEventRecord(evRoot, 0);
    cudaStreamWaitEvent(s1, evRoot, 0);
    k_csr<<<CSR_BLOCKS, CSR_THREADS, 0, s1>>>(ei);
    cudaEventRecord(evCsr, s1);

    // layer-1 GEMM: x -> [v (half2) | s (fp32)]
    k_mma<256><<<148, 256, SM1>>>(x, Wrel1, Wroot1, b1,
                                  (float*)p_s, (uint32_t*)p_v16);

    // join CSR, then aggregate + relu -> fp16 t1
    cudaStreamWaitEvent(0, evCsr, 0);
    k_agg1<<<(N_NODES * 32 + 255) / 256, 256>>>((const uint2*)p_v16,
                                                (const float4*)p_s, (uint2*)p_t16);

    // layer-2 GEMM: t16 -> [u (half2) | r (fp32)]
    k_mma2<<<148, 256, SM2>>>((const uint32_t*)p_t16, Wrel2, Wroot2, b2,
                              (float*)p_r, (uint32_t*)p_u16);

    // final aggregation (fp16 gathers, fp32 accumulate)
    k_agg2<<<(N_NODES * 32 + 255) / 256, 256>>>((const uint32_t*)p_u16,
                                                (const float2*)p_r, (float2*)d_out);
}

// round 17
// speedup vs baseline: 1.1436x; 1.1436x over previous
#include <cuda_runtime.h>
#include <cuda_bf16.h>
#include <cuda_fp16.h>
#include <cstdint>

#define N_NODES 50000
#define N_EDGES 800000

#define SCAN_BLK 256
#define NBLK ((N_NODES + SCAN_BLK - 1) / SCAN_BLK)   // 196
#define NT128 ((N_NODES + 127) / 128)                // 391

typedef unsigned long long ull;

// ---------------- device scratch (static, no allocation) ----------------
__device__ uint32_t g_v16[N_NODES * 64];   // layer1 v, half2 pairs (256 B/row)
__device__ float    g_s  [N_NODES * 128];  // layer1 s (= x.Wroot1 + b1), fp32
__device__ uint32_t g_t16[N_NODES * 64];   // layer1 activations, half2 (256 B/row)
__device__ uint32_t g_u16[N_NODES * 32];   // layer2 u, half2 pairs (128 B/row)
__device__ float    g_r  [N_NODES * 64];   // layer2 r (= t1.Wroot2 + b2), fp32
__device__ int      g_deg[N_NODES];
__device__ int      g_off[N_NODES + 1];
__device__ int      g_cursor[N_NODES];
__device__ int      g_csr[N_EDGES];
__device__ int      g_flag[NBLK];          // 0=invalid 1=aggregate 2=prefix
__device__ int      g_aggv[NBLK];
__device__ int      g_prefv[NBLK];
__device__ int      g_is64;

// ================= CSR build (R15-proven 4-kernel chain) =================
__global__ void k_zero_detect(const int* __restrict__ ei32) {
    int i = blockIdx.x * blockDim.x + threadIdx.x;
    if (i < N_NODES) g_deg[i] = 0;
    if (i < NBLK) g_flag[i] = 0;
    if (i == 0) {
        int orv = 0;
#pragma unroll
        for (int k = 0; k < 64; k++) orv |= ei32[2 * k + 1];
        g_is64 = (orv == 0) ? 1 : 0;
    }
}

__global__ void k_hist(const void* __restrict__ ei) {
    int e0 = (blockIdx.x * blockDim.x + threadIdx.x) * 4;
    if (e0 >= N_EDGES) return;
    int d0, d1, d2, d3;
    if (g_is64) {
        const longlong2* p = (const longlong2*)((const long long*)ei + N_EDGES);
        longlong2 a = p[e0 >> 1];
        longlong2 b = p[(e0 >> 1) + 1];
        d0 = (int)a.x; d1 = (int)a.y; d2 = (int)b.x; d3 = (int)b.y;
    } else {
        int4 a = *(const int4*)((const int*)ei + N_EDGES + e0);
        d0 = a.x; d1 = a.y; d2 = a.z; d3 = a.w;
    }
    atomicAdd(&g_deg[d0], 1);
    atomicAdd(&g_deg[d1], 1);
    atomicAdd(&g_deg[d2], 1);
    atomicAdd(&g_deg[d3], 1);
}

__global__ void k_scan() {
    __shared__ int sh[SCAN_BLK];
    __shared__ int s_base;
    const int t = threadIdx.x;
    const int bid = blockIdx.x;
    int i = bid * SCAN_BLK + t;
    int v = (i < N_NODES) ? g_deg[i] : 0;
    sh[t] = v;
    __syncthreads();
    for (int off = 1; off < SCAN_BLK; off <<= 1) {
        int add = (t >= off) ? sh[t - off] : 0;
        __syncthreads();
        sh[t] += add;
        __syncthreads();
    }
    const int total = sh[SCAN_BLK - 1];

    volatile int* vflag = (volatile int*)g_flag;
    volatile int* vagg  = (volatile int*)g_aggv;
    volatile int* vpref = (volatile int*)g_prefv;

    if (bid == 0) {
        if (t == 0) {
            g_prefv[0] = total;
            __threadfence();
            vflag[0] = 2;
            s_base = 0;
        }
    } else {
        if (t == 0) {
            g_aggv[bid] = total;
            __threadfence();
            vflag[bid] = 1;
        }
        __syncwarp(0xFFFFFFFF);
        if (t < 32) {
            int base = 0;
            int wstart = bid - 1;
            bool done = false;
            while (!done) {
                int j = wstart - t;
                int f;
                do {
                    f = (j >= 0) ? vflag[j] : 2;
                } while (__any_sync(0xFFFFFFFF, f == 0));
                __threadfence();
                unsigned ball = __ballot_sync(0xFFFFFFFF, f == 2);
                if (ball) {
                    int lead = __ffs(ball) - 1;
                    int contrib = 0;
                    if (t < lead) contrib = vagg[j];
                    else if (t == lead) contrib = (j >= 0) ? vpref[j] : 0;
#pragma unroll
                    for (int s = 16; s; s >>= 1)
                        contrib += __shfl_down_sync(0xFFFFFFFF, contrib, s);
                    if (t == 0) base += contrib;
                    done = true;
                } else {
                    int contrib = vagg[j];
#pragma unroll
                    for (int s = 16; s; s >>= 1)
                        contrib += __shfl_down_sync(0xFFFFFFFF, contrib, s);
                    if (t == 0) base += contrib;
                    wstart -= 32;
                }
            }
            if (t == 0) {
                g_prefv[bid] = base + total;
                __threadfence();
                vflag[bid] = 2;
                s_base = base;
            }
        }
    }
    __syncthreads();
    const int base = s_base;
    if (i < N_NODES) {
        int o = base + sh[t] - v;
        g_off[i] = o;
        g_cursor[i] = o;
    }
    if (bid == NBLK - 1 && t == 0) g_off[N_NODES] = N_EDGES;
}

__global__ void k_scatter(const void* __restrict__ ei) {
    int e0 = (blockIdx.x * blockDim.x + threadIdx.x) * 4;
    if (e0 >= N_EDGES) return;
    int s0, s1, s2, s3, d0, d1, d2, d3;
    if (g_is64) {
        const longlong2* ps = (const longlong2*)ei;
        const longlong2* pd = (const longlong2*)((const long long*)ei + N_EDGES);
        longlong2 sa = ps[e0 >> 1], sb = ps[(e0 >> 1) + 1];
        longlong2 da = pd[e0 >> 1], db = pd[(e0 >> 1) + 1];
        s0 = (int)sa.x; s1 = (int)sa.y; s2 = (int)sb.x; s3 = (int)sb.y;
        d0 = (int)da.x; d1 = (int)da.y; d2 = (int)db.x; d3 = (int)db.y;
    } else {
        int4 sa = *(const int4*)((const int*)ei + e0);
        int4 da = *(const int4*)((const int*)ei + N_EDGES + e0);
        s0 = sa.x; s1 = sa.y; s2 = sa.z; s3 = sa.w;
        d0 = da.x; d1 = da.y; d2 = da.z; d3 = da.w;
    }
    int p0 = atomicAdd(&g_cursor[d0], 1);
    int p1 = atomicAdd(&g_cursor[d1], 1);
    int p2 = atomicAdd(&g_cursor[d2], 1);
    int p3 = atomicAdd(&g_cursor[d3], 1);
    g_csr[p0] = s0;
    g_csr[p1] = s1;
    g_csr[p2] = s2;
    g_csr[p3] = s3;
}

// ================= split helpers =================
__device__ __forceinline__ void decomp2(float x, float y, uint32_t& hp, uint32_t& lp) {
    __nv_bfloat16 hx = __float2bfloat16(x);
    __nv_bfloat16 hy = __float2bfloat16(y);
    float rx = x - __bfloat162float(hx);
    float ry = y - __bfloat162float(hy);
    __nv_bfloat16 lx = __float2bfloat16(rx);
    __nv_bfloat16 ly = __float2bfloat16(ry);
    hp = (uint32_t)__bfloat16_as_ushort(hx) | ((uint32_t)__bfloat16_as_ushort(hy) << 16);
    lp = (uint32_t)__bfloat16_as_ushort(lx) | ((uint32_t)__bfloat16_as_ushort(ly) << 16);
}

__device__ __forceinline__ void mma16816(float* c, const uint32_t* a, uint2 b) {
    asm volatile(
        "mma.sync.aligned.m16n8k16.row.col.f32.bf16.bf16.f32 "
        "{%0,%1,%2,%3}, {%4,%5,%6,%7}, {%8,%9}, {%0,%1,%2,%3};"
        : "+f"(c[0]), "+f"(c[1]), "+f"(c[2]), "+f"(c[3])
        : "r"(a[0]), "r"(a[1]), "r"(a[2]), "r"(a[3]), "r"(b.x), "r"(b.y));
}

__device__ __forceinline__ void mma16816h(float* c, const uint32_t* a, uint2 b) {
    asm volatile(
        "mma.sync.aligned.m16n8k16.row.col.f32.f16.f16.f32 "
        "{%0,%1,%2,%3}, {%4,%5,%6,%7}, {%8,%9}, {%0,%1,%2,%3};"
        : "+f"(c[0]), "+f"(c[1]), "+f"(c[2]), "+f"(c[3])
        : "r"(a[0]), "r"(a[1]), "r"(a[2]), "r"(a[3]), "r"(b.x), "r"(b.y));
}

__device__ __forceinline__ uint32_t pack_h2(float a, float b) {
    __half2 h = __floats2half2_rn(a, b);
    return *(uint32_t*)&h;
}

// ================= layer-1 GEMM (fp32 input, 3-pass bf16 split — R13-proven) =================
template <int NCOLS>
__global__ void __launch_bounds__(256, 1)
k_mma(const float* __restrict__ X,
      const float* __restrict__ Wa, const float* __restrict__ Wb,
      const float* __restrict__ bias,
      float* __restrict__ out32, uint32_t* __restrict__ out16) {
    constexpr int NT   = NCOLS / 8;
    constexpr int HB   = NCOLS / 2;
    constexpr int MT_W = (NCOLS == 256) ? 2 : 1;
    constexpr int NT_W = 16;
    extern __shared__ uint32_t sm[];
    uint32_t* Ah = sm;
    uint32_t* Al = sm + 8192;
    uint32_t* Bh = sm + 16384;
    uint32_t* Bl = Bh + NT * 512;

    const int tid = threadIdx.x;
    const int w = tid >> 5, lane = tid & 31;
    const int wm = (NCOLS == 256) ? (w >> 1) : w;
    const int wn = (NCOLS == 256) ? (w & 1) : 0;

    for (int idx = tid; idx < NCOLS * 64; idx += 256) {
        int h  = idx >> 6;
        int c2 = (idx & 63) << 1;
        const float* src = (h < HB) ? (Wa + h * 128 + c2) : (Wb + (h - HB) * 128 + c2);
        float2 wv = *(const float2*)src;
        uint32_t hp, lp;
        decomp2(wv.x, wv.y, hp, lp);
        int nt = h >> 3;
        int ln = ((h & 7) << 2) | ((c2 >> 1) & 3);
        int ks = c2 >> 4;
        int rg = (c2 >> 3) & 1;
        int addr = ((ks * NT + nt) * 32 + ln) * 2 + rg;
        Bh[addr] = hp;
        Bl[addr] = lp;
    }
    __syncthreads();

    for (int tile = blockIdx.x; tile < NT128; tile += gridDim.x) {
        const int n0 = tile << 7;

        for (int idx = tid; idx < 128 * 64; idx += 256) {
            int r  = idx >> 6;
            int c2 = (idx & 63) << 1;
            int n = n0 + r;
            float2 v = (n < N_NODES) ? *(const float2*)(X + (size_t)n * 128 + c2)
                                     : make_float2(0.f, 0.f);
            uint32_t hp, lp;
            decomp2(v.x, v.y, hp, lp);
            int mt = r >> 4, rr = r & 15;
            int ln = ((rr & 7) << 2) | ((c2 >> 1) & 3);
            int ks = c2 >> 4;
            int rg = ((rr >> 3) & 1) | (((c2 >> 3) & 1) << 1);
            int addr = (((ks << 3) | mt) * 32 + ln) * 4 + rg;
            Ah[addr] = hp;
            Al[addr] = lp;
        }
        __syncthreads();

        float acc[MT_W][NT_W][4];
#pragma unroll
        for (int m = 0; m < MT_W; m++)
#pragma unroll
            for (int t = 0; t < NT_W; t++)
#pragma unroll
                for (int c = 0; c < 4; c++) acc[m][t][c] = 0.f;

        const uint32_t* Ap[3] = { Ah, Ah, Al };
        const uint32_t* Bp[3] = { Bh, Bl, Bh };
#pragma unroll
        for (int p = 0; p < 3; p++) {
            const uint32_t* A = Ap[p];
            const uint32_t* B = Bp[p];
#pragma unroll
            for (int ks = 0; ks < 8; ks++) {
                uint32_t af[MT_W][4];
#pragma unroll
                for (int m = 0; m < MT_W; m++) {
                    int mt = wm * MT_W + m;
                    uint4 v = *(const uint4*)&A[(((ks << 3) | mt) * 32 + lane) * 4];
                    af[m][0] = v.x; af[m][1] = v.y; af[m][2] = v.z; af[m][3] = v.w;
                }
#pragma unroll
                for (int t = 0; t < NT_W; t++) {
                    int nt = wn * NT_W + t;
                    uint2 bv = *(const uint2*)&B[((ks * NT + nt) * 32 + lane) * 2];
#pragma unroll
                    for (int m = 0; m < MT_W; m++)
                        mma16816(acc[m][t], af[m], bv);
                }
            }
        }
        __syncthreads();

#pragma unroll
        for (int m = 0; m < MT_W; m++) {
            int row0 = n0 + (wm * MT_W + m) * 16 + (lane >> 2);
#pragma unroll
            for (int t = 0; t < NT_W; t++) {
                int col = (wn * NT_W + t) * 8 + ((lane & 3) << 1);
                if (col < HB) {
                    if (row0 < N_NODES)
                        out16[(size_t)row0 * (HB / 2) + (col >> 1)] =
                            pack_h2(acc[m][t][0], acc[m][t][1]);
                    if (row0 + 8 < N_NODES)
                        out16[(size_t)(row0 + 8) * (HB / 2) + (col >> 1)] =
                            pack_h2(acc[m][t][2], acc[m][t][3]);
                } else {
                    int cc = col - HB;
                    float bx = __ldg(&bias[cc]);
                    float by = __ldg(&bias[cc + 1]);
                    if (row0 < N_NODES)
                        *(float2*)&out32[(size_t)row0 * HB + cc] =
                            make_float2(acc[m][t][0] + bx, acc[m][t][1] + by);
                    if (row0 + 8 < N_NODES)
                        *(float2*)&out32[(size_t)(row0 + 8) * HB + cc] =
                            make_float2(acc[m][t][2] + bx, acc[m][t][3] + by);
                }
            }
        }
    }
}

// ================= layer-2 GEMM: single-pass fp16, 3 blocks/SM =================
__global__ void __launch_bounds__(256, 3)
k_mma2(const uint32_t* __restrict__ T16,
       const float* __restrict__ Wa, const float* __restrict__ Wb,
       const float* __restrict__ bias,
       float* __restrict__ out32, uint32_t* __restrict__ out16) {
    constexpr int NT = 16, HB = 64, NT_W = 16;
    extern __shared__ uint32_t sm[];
    uint32_t* Ah = sm;            // 8192 u32
    uint32_t* Bh = sm + 8192;     // 8192 u32

    const int tid = threadIdx.x;
    const int w = tid >> 5, lane = tid & 31;

    for (int idx = tid; idx < 128 * 64; idx += 256) {
        int h  = idx >> 6;
        int c2 = (idx & 63) << 1;
        const float* src = (h < HB) ? (Wa + h * 128 + c2) : (Wb + (h - HB) * 128 + c2);
        float2 wv = *(const float2*)src;
        uint32_t hp = pack_h2(wv.x, wv.y);
        int nt = h >> 3;
        int ln = ((h & 7) << 2) | ((c2 >> 1) & 3);
        int ks = c2 >> 4;
        int rg = (c2 >> 3) & 1;
        Bh[((ks * NT + nt) * 32 + ln) * 2 + rg] = hp;
    }
    __syncthreads();

    for (int tile = blockIdx.x; tile < NT128; tile += gridDim.x) {
        const int n0 = tile << 7;

        for (int idx = tid; idx < 128 * 64; idx += 256) {
            int r  = idx >> 6;
            int cu = idx & 63;
            int n = n0 + r;
            uint32_t a = (n < N_NODES) ? T16[(size_t)n * 64 + cu] : 0u;
            int mt = r >> 4, rr = r & 15;
            int ln = ((rr & 7) << 2) | (cu & 3);
            int ks = cu >> 3;
            int rg = ((rr >> 3) & 1) | (((cu >> 2) & 1) << 1);
            Ah[(((ks << 3) | mt) * 32 + ln) * 4 + rg] = a;
        }
        __syncthreads();

        float acc[NT_W][4];
#pragma unroll
        for (int t = 0; t < NT_W; t++)
#pragma unroll
            for (int c = 0; c < 4; c++) acc[t][c] = 0.f;

#pragma unroll
        for (int ks = 0; ks < 8; ks++) {
            uint32_t af[4];
            uint4 v = *(const uint4*)&Ah[(((ks << 3) | w) * 32 + lane) * 4];
            af[0] = v.x; af[1] = v.y; af[2] = v.z; af[3] = v.w;
#pragma unroll
            for (int t = 0; t < NT_W; t++) {
                uint2 bv = *(const uint2*)&Bh[((ks * NT + t) * 32 + lane) * 2];
                mma16816h(acc[t], af, bv);
            }
        }
        __syncthreads();

        int row0 = n0 + w * 16 + (lane >> 2);
#pragma unroll
        for (int t = 0; t < NT_W; t++) {
            int col = t * 8 + ((lane & 3) << 1);
            if (col < HB) {
                if (row0 < N_NODES)
                    out16[(size_t)row0 * (HB / 2) + (col >> 1)] =
                        pack_h2(acc[t][0], acc[t][1]);
                if (row0 + 8 < N_NODES)
                    out16[(size_t)(row0 + 8) * (HB / 2) + (col >> 1)] =
                        pack_h2(acc[t][2], acc[t][3]);
            } else {
                int cc = col - HB;
                float bx = __ldg(&bias[cc]);
                float by = __ldg(&bias[cc + 1]);
                if (row0 < N_NODES)
                    *(float2*)&out32[(size_t)row0 * HB + cc] =
                        make_float2(acc[t][0] + bx, acc[t][1] + by);
                if (row0 + 8 < N_NODES)
                    *(float2*)&out32[(size_t)(row0 + 8) * HB + cc] =
                        make_float2(acc[t][2] + bx, acc[t][3] + by);
            }
        }
    }
}

// ================= aggregations =================
__global__ void k_agg1(const uint2* __restrict__ v16, const float4* __restrict__ s,
                       uint2* __restrict__ t16) {
    int gw = (blockIdx.x * blockDim.x + threadIdx.x) >> 5;
    int lane = threadIdx.x & 31;
    if (gw >= N_NODES) return;
    int beg = g_off[gw], end = g_off[gw + 1];
    float4 acc = s[gw * 32 + lane];
    int j = beg;
    for (; j + 8 <= end; j += 8) {
        uint2 rv[8];
#pragma unroll
        for (int q = 0; q < 8; q++) rv[q] = v16[g_csr[j + q] * 32 + lane];
#pragma unroll
        for (int q = 0; q < 8; q++) {
            float2 lo = __half22float2(*(const __half2*)&rv[q].x);
            float2 hi = __half22float2(*(const __half2*)&rv[q].y);
            acc.x += lo.x; acc.y += lo.y; acc.z += hi.x; acc.w += hi.y;
        }
    }
    for (; j < end; j++) {
        uint2 a = v16[g_csr[j] * 32 + lane];
        float2 lo = __half22float2(*(const __half2*)&a.x);
        float2 hi = __half22float2(*(const __half2*)&a.y);
        acc.x += lo.x; acc.y += lo.y; acc.z += hi.x; acc.w += hi.y;
    }
    acc.x = fmaxf(acc.x, 0.f); acc.y = fmaxf(acc.y, 0.f);
    acc.z = fmaxf(acc.z, 0.f); acc.w = fmaxf(acc.w, 0.f);
    uint2 o;
    o.x = pack_h2(acc.x, acc.y);
    o.y = pack_h2(acc.z, acc.w);
    t16[gw * 32 + lane] = o;
}

__global__ void k_agg2(const uint32_t* __restrict__ u16, const float2* __restrict__ r,
                       float2* __restrict__ out) {
    int gw = (blockIdx.x * blockDim.x + threadIdx.x) >> 5;
    int lane = threadIdx.x & 31;
    if (gw >= N_NODES) return;
    int beg = g_off[gw], end = g_off[gw + 1];
    float2 acc = r[gw * 32 + lane];
    int j = beg;
    for (; j + 8 <= end; j += 8) {
        uint32_t rv[8];
#pragma unroll
        for (int q = 0; q < 8; q++) rv[q] = u16[g_csr[j + q] * 32 + lane];
#pragma unroll
        for (int q = 0; q < 8; q++) {
            float2 av = __half22float2(*(const __half2*)&rv[q]);
            acc.x += av.x; acc.y += av.y;
        }
    }
    for (; j < end; j++) {
        uint32_t a = u16[g_csr[j] * 32 + lane];
        float2 av = __half22float2(*(const __half2*)&a);
        acc.x += av.x; acc.y += av.y;
    }
    out[gw * 32 + lane] = acc;
}

// ================= launch =================
extern "C" void kernel_launch(void* const* d_in, const int* in_sizes, int n_in,
                              void* d_out, int out_size) {
    const float* x      = (const float*)d_in[0];
    const void*  ei     = d_in[1];
    const float* Wrel1  = (const float*)d_in[2];
    const float* Wroot1 = (const float*)d_in[3];
    const float* b1     = (const float*)d_in[4];
    const float* Wrel2  = (const float*)d_in[5];
    const float* Wroot2 = (const float*)d_in[6];
    const float* b2     = (const float*)d_in[7];

    void *p_v16 = nullptr, *p_s = nullptr, *p_t16 = nullptr;
    void *p_u16 = nullptr, *p_r = nullptr;
    cudaGetSymbolAddress(&p_v16, g_v16);
    cudaGetSymbolAddress(&p_s, g_s);
    cudaGetSymbolAddress(&p_t16, g_t16);
    cudaGetSymbolAddress(&p_u16, g_u16);
    cudaGetSymbolAddress(&p_r, g_r);

    const int SM1 = (16384 + 2 * 32 * 512) * 4;   // 196,608 B (A hi/lo + B hi/lo)
    const int SM2 = 16384 * 4;                    //  65,536 B
    cudaFuncSetAttribute((const void*)k_mma<256>,
                         cudaFuncAttributeMaxDynamicSharedMemorySize, SM1);
    cudaFuncSetAttribute((const void*)k_mma2,
                         cudaFuncAttributeMaxDynamicSharedMemorySize, SM2);

    static cudaStream_t s1 = nullptr;
    static cudaEvent_t evRoot = nullptr, evCsr = nullptr;
    if (s1 == nullptr) {
        cudaStreamCreateWithFlags(&s1, cudaStreamNonBlocking);
        cudaEventCreateWithFlags(&evRoot, cudaEventDisableTiming);
        cudaEventCreateWithFlags(&evCsr, cudaEventDisableTiming);
    }

    // fork: CSR build on s1, concurrent with layer-1 GEMM on stream 0
    cudaEventRecord(evRoot, 0);
    cudaStreamWaitEvent(s1, evRoot, 0);
    k_zero_detect<<<(N_NODES + 255) / 256, 256, 0, s1>>>((const int*)ei);
    k_hist<<<(N_EDGES / 4 + 255) / 256, 256, 0, s1>>>(ei);
    k_scan<<<NBLK, SCAN_BLK, 0, s1>>>();
    k_scatter<<<(N_EDGES / 4 + 255) / 256, 256, 0, s1>>>(ei);
    cudaEventRecord(evCsr, s1);

    // layer-1 GEMM: x -> [v (half2) | s (fp32)]
    k_mma<256><<<148, 256, SM1>>>(x, Wrel1, Wroot1, b1,
                                  (float*)p_s, (uint32_t*)p_v16);

    // join CSR, then aggregate + relu -> fp16 t1
    cudaStreamWaitEvent(0, evCsr, 0);
    k_agg1<<<(N_NODES * 32 + 255) / 256, 256>>>((const uint2*)p_v16,
                                                (const float4*)p_s, (uint2*)p_t16);

    // layer-2 GEMM: t16 -> [u (half2) | r (fp32)], 3 blocks/SM for latency hiding
    k_mma2<<<444, 256, SM2>>>((const uint32_t*)p_t16, Wrel2, Wroot2, b2,
                              (float*)p_r, (uint32_t*)p_u16);

    // final aggregation (fp16 gathers, fp32 accumulate)
    k_agg2<<<(N_NODES * 32 + 255) / 256, 256>>>((const uint32_t*)p_u16,
                                                (const float2*)p_r, (float2*)d_out);
}